// round 12
// baseline (speedup 1.0000x reference)
#include <cuda_runtime.h>
#include <math.h>
#include <cstdint>

#define O_DIM 2048
#define I_DIM 2048
#define OB 8
#define GO (O_DIM / OB)      // 256 o-chunks
#define GI 4                 // i split
#define IB (I_DIM / GI)      // 512 i-rows per block
#define TB 128               // 4 warps; each warp owns 128 i-rows
#define NWARP 4
#define WIB 128              // i-rows per warp
#define WSTAGE_FLOATS (WIB * 9)          // 1152 floats per warp-stage
#define WSTAGE_BYTES (WSTAGE_FLOATS * 4) // 4608 bytes
#define MBAR_OFF (NWARP * 2 * WSTAGE_BYTES)   // 36864
#define TAIL_F (MBAR_OFF / 4 + 32)            // float idx past mbars (128B pad)
#define SMEM_DYN ((TAIL_F + 160) * 4)
#define U_ELEMS 30720        // |u1|+|u2|+|u3| = 6144+6144+18432
#define SCR_STRIDE 30720

typedef unsigned long long u64t;

// ---------------- persistent device state (static, no allocation) ----------
__device__ __align__(16) float g_v1[O_DIM * 3];
__device__ __align__(16) float g_v2[O_DIM * 3];
__device__ __align__(16) float g_v3[O_DIM];
__device__ __align__(16) float g_v4[I_DIM];
__device__ __align__(16) float g_u1[I_DIM * 3];
__device__ __align__(16) float g_u2[I_DIM * 3];
__device__ __align__(16) float g_u3[I_DIM * 9];
__device__ __align__(16) float g_u4[O_DIM * 9];
__device__ __align__(16) float g_scr[(size_t)GO * SCR_STRIDE];  // u123 partials
__device__ float g_vss[4];  // ||v_m||^2 (final iter)
__device__ float g_wss[4];  // ||w_m||^2 (final iter)

// ---------------- helpers ----------------
__device__ __forceinline__ uint32_t smem_u32_of(const void* p) {
    uint32_t a;
    asm("{ .reg .u64 t; cvta.to.shared.u64 t, %1; cvt.u32.u64 %0, t; }"
        : "=r"(a) : "l"(p));
    return a;
}
__device__ __forceinline__ void mbar_init(uint32_t mbar, uint32_t cnt) {
    asm volatile("mbarrier.init.shared.b64 [%0], %1;" :: "r"(mbar), "r"(cnt) : "memory");
}
__device__ __forceinline__ void mbar_expect_tx(uint32_t mbar, uint32_t bytes) {
    asm volatile("mbarrier.arrive.expect_tx.shared.b64 _, [%0], %1;"
                 :: "r"(mbar), "r"(bytes) : "memory");
}
__device__ __forceinline__ void mbar_wait(uint32_t mbar, uint32_t parity) {
    asm volatile(
        "{\n\t"
        ".reg .pred P1;\n\t"
        "W_%=:\n\t"
        "mbarrier.try_wait.parity.acquire.cta.shared::cta.b64 P1, [%0], %1, 0x989680;\n\t"
        "@P1 bra D_%=;\n\t"
        "bra W_%=;\n\t"
        "D_%=:\n\t"
        "}"
        :: "r"(mbar), "r"(parity) : "memory");
}
__device__ __forceinline__ void bulk_g2s(uint32_t dst, const void* src,
                                         uint32_t bytes, uint32_t mbar) {
    asm volatile(
        "cp.async.bulk.shared::cta.global.mbarrier::complete_tx::bytes [%0], [%1], %2, [%3];"
        :: "r"(dst), "l"(src), "r"(bytes), "r"(mbar) : "memory");
}
__device__ __forceinline__ void fence_async() {
    asm volatile("fence.proxy.async.shared::cta;" ::: "memory");
}

// packed fp32x2
__device__ __forceinline__ void fma2(u64t& d, u64t a, u64t b) {
    asm("fma.rn.f32x2 %0, %1, %2, %0;" : "+l"(d) : "l"(a), "l"(b));
}
__device__ __forceinline__ u64t pk2(float lo, float hi) {
    u64t r; asm("mov.b64 %0, {%1, %2};" : "=l"(r) : "f"(lo), "f"(hi)); return r;
}
__device__ __forceinline__ float2 upk(u64t v) {
    float2 r; asm("mov.b64 {%0, %1}, %2;" : "=f"(r.x), "=f"(r.y) : "l"(v)); return r;
}

__device__ __forceinline__ float block_sum1024(float v) {
    __shared__ float sred[32];
#pragma unroll
    for (int s = 16; s > 0; s >>= 1) v += __shfl_xor_sync(0xffffffffu, v, s);
    if ((threadIdx.x & 31) == 0) sred[threadIdx.x >> 5] = v;
    __syncthreads();
    if (threadIdx.x < 32) {
        v = sred[threadIdx.x];
#pragma unroll
        for (int s = 16; s > 0; s >>= 1) v += __shfl_xor_sync(0xffffffffu, v, s);
    }
    return v;  // valid on thread 0
}

__device__ __forceinline__ void ld4(float* dst, const float* src) {
    float4 a = *(const float4*)src;
    dst[0] = a.x; dst[1] = a.y; dst[2] = a.z; dst[3] = a.w;
}

// ---------------- tiny kernels ----------------
__global__ void zero_v_kernel() {
    int idx = blockIdx.x * 1024 + threadIdx.x;  // grid 6 x 1024 = 6144
    if (idx < O_DIM * 3) { g_v1[idx] = 0.f; g_v2[idx] = 0.f; }
    if (idx < O_DIM)     { g_v3[idx] = 0.f; g_v4[idx] = 0.f; }
    if (idx < 4)         g_vss[idx] = 0.f;
}

// blocks 0..15: sumsq of v's into g_vss ; blocks 16..33: zero g_u4 (+g_wss)
__global__ void vnorm_zero_kernel() {
    const int b = blockIdx.x, t = threadIdx.x;
    if (b < 16) {
        const int e = b * 1024 + t;
        float val;
        int mode;
        if (b < 6)       { val = g_v1[e];          mode = 0; }
        else if (b < 12) { val = g_v2[e - 6144];   mode = 1; }
        else if (b < 14) { val = g_v3[e - 12288];  mode = 2; }
        else             { val = g_v4[e - 14336];  mode = 3; }
        float tot = block_sum1024(val * val);
        if (t == 0) atomicAdd(&g_vss[mode], tot);
    } else {
        const int e = (b - 16) * 1024 + t;
        if (e < O_DIM * 9) g_u4[e] = 0.f;
        if (b == 16 && t < 4) g_wss[t] = 0.f;
    }
}

// ---------------- V-pass: v = contract(K, u) for all 4 modes ----------------
// Warp w owns i-rows [128w,128w+128) with a PRIVATE double-buffered pipeline.
// FORWARD o traversal (pairs with upass's REVERSE for L2 ping-pong reuse).
__global__ void __launch_bounds__(TB) vpass_kernel(
    const float* __restrict__ K,
    const float* eu1, const float* eu2, const float* eu3, const float* eu4,
    int use_ext) {
    extern __shared__ __align__(16) float smem[];
    const uint32_t sbase = smem_u32_of(smem);
    float* u4s = smem + TAIL_F;  // 72 floats

    const float* u1 = use_ext ? eu1 : g_u1;
    const float* u2 = use_ext ? eu2 : g_u2;
    const float* u3 = use_ext ? eu3 : g_u3;
    const float* u4 = use_ext ? eu4 : g_u4;

    const int t = threadIdx.x;
    const int wi = t >> 5, l = t & 31;
    const int ob = blockIdx.x * OB;
    const int by = blockIdx.y;

    const float* Kw = K + ((size_t)ob * I_DIM + by * IB + wi * WIB) * 9;
    const size_t ostr = (size_t)I_DIM * 9;
    const int i0 = by * IB + wi * WIB + l * 4;  // 4 consecutive i-rows
    float* bufw = smem + wi * 2 * WSTAGE_FLOATS;
    const uint32_t bufw_a = sbase + wi * 2 * WSTAGE_BYTES;
    const uint32_t mb0 = sbase + MBAR_OFF + wi * 16;
    const uint32_t mb1 = mb0 + 8;

    for (int j = t; j < OB * 9; j += TB) u4s[j] = u4[ob * 9 + j];
    if (t == 0) {
#pragma unroll
        for (int b = 0; b < 2 * NWARP; b++) mbar_init(sbase + MBAR_OFF + b * 8, 1);
        fence_async();
    }
    __syncthreads();
    if (l == 0) {  // each warp's lane0 drives its own pipeline
        mbar_expect_tx(mb0, WSTAGE_BYTES);
        bulk_g2s(bufw_a, Kw, WSTAGE_BYTES, mb0);
        mbar_expect_tx(mb1, WSTAGE_BYTES);
        bulk_g2s(bufw_a + WSTAGE_BYTES, Kw + ostr, WSTAGE_BYTES, mb1);
    }

    // pack u operands along (row, row+1) pairs
    u64t u1pr[6], u2pr[6], u3pr[18];
    {
        float a[12], b[12], c3[36];
#pragma unroll
        for (int q = 0; q < 3; q++) ld4(a + q * 4, u1 + i0 * 3 + q * 4);
#pragma unroll
        for (int q = 0; q < 3; q++) ld4(b + q * 4, u2 + i0 * 3 + q * 4);
#pragma unroll
        for (int q = 0; q < 9; q++) ld4(c3 + q * 4, u3 + i0 * 9 + q * 4);
#pragma unroll
        for (int pi = 0; pi < 2; pi++) {
#pragma unroll
            for (int w = 0; w < 3; w++) {
                u1pr[pi * 3 + w] = pk2(a[pi * 6 + w], a[pi * 6 + 3 + w]);
                u2pr[pi * 3 + w] = pk2(b[pi * 6 + w], b[pi * 6 + 3 + w]);
            }
#pragma unroll
            for (int p = 0; p < 9; p++)
                u3pr[pi * 9 + p] = pk2(c3[pi * 18 + p], c3[pi * 18 + 9 + p]);
        }
    }

    u64t v4acc[2] = {0ull, 0ull};

#pragma unroll 1
    for (int s = 0; s < OB; s++) {
        mbar_wait((s & 1) ? mb1 : mb0, (s >> 1) & 1);

        const float* kb = bufw + (s & 1) * WSTAGE_FLOATS + l * 36;
        float kk[36];
#pragma unroll
        for (int q = 0; q < 9; q++) ld4(kk + q * 4, kb + q * 4);

        u64t cd[9];
#pragma unroll
        for (int p = 0; p < 9; p++) {
            const float c = u4s[s * 9 + p];
            cd[p] = pk2(c, c);
        }

        u64t acc1[3] = {0ull, 0ull, 0ull};
        u64t acc2[3] = {0ull, 0ull, 0ull};
        u64t acc3 = 0ull;
#pragma unroll
        for (int pi = 0; pi < 2; pi++) {
#pragma unroll
            for (int p = 0; p < 9; p++) {
                const int h = p / 3, w = p - h * 3;
                const u64t kp = pk2(kk[pi * 18 + p], kk[pi * 18 + 9 + p]);
                fma2(acc1[h], kp, u1pr[pi * 3 + w]);
                fma2(acc2[w], kp, u2pr[pi * 3 + h]);
                fma2(acc3, kp, u3pr[pi * 9 + p]);
                fma2(v4acc[pi], kp, cd[p]);
            }
        }

        float r[7];
#pragma unroll
        for (int j = 0; j < 3; j++) {
            float2 f1 = upk(acc1[j]); r[j] = f1.x + f1.y;
            float2 f2 = upk(acc2[j]); r[3 + j] = f2.x + f2.y;
        }
        { float2 f3 = upk(acc3); r[6] = f3.x + f3.y; }
#pragma unroll
        for (int j = 0; j < 7; j++)
#pragma unroll
            for (int sh = 16; sh > 0; sh >>= 1)
                r[j] += __shfl_xor_sync(0xffffffffu, r[j], sh);
        if (l == 0) {
            const int o = ob + s;
            atomicAdd(&g_v1[o * 3 + 0], r[0]);
            atomicAdd(&g_v1[o * 3 + 1], r[1]);
            atomicAdd(&g_v1[o * 3 + 2], r[2]);
            atomicAdd(&g_v2[o * 3 + 0], r[3]);
            atomicAdd(&g_v2[o * 3 + 1], r[4]);
            atomicAdd(&g_v2[o * 3 + 2], r[5]);
            atomicAdd(&g_v3[o], r[6]);
            // refill just-consumed buffer with stage s+2 (warp-private:
            // all lanes' LDS of this buffer precede this issue in program order)
            if (s + 2 < OB) {
                const uint32_t mb = (s & 1) ? mb1 : mb0;
                mbar_expect_tx(mb, WSTAGE_BYTES);
                bulk_g2s(bufw_a + (s & 1) * WSTAGE_BYTES,
                         Kw + (size_t)(s + 2) * ostr, WSTAGE_BYTES, mb);
            }
        }
    }

    float2 fa = upk(v4acc[0]), fb = upk(v4acc[1]);
    atomicAdd(&g_v4[i0 + 0], fa.x);
    atomicAdd(&g_v4[i0 + 1], fa.y);
    atomicAdd(&g_v4[i0 + 2], fb.x);
    atomicAdd(&g_v4[i0 + 3], fb.y);
}

// ------- U-pass stage 1: w = contract(K, v), REVERSE o traversal -----------
// Reads the o-rows the preceding vpass touched LAST, first -> L2 ping-pong.
__global__ void __launch_bounds__(TB) upass_kernel(const float* __restrict__ K) {
    extern __shared__ __align__(16) float smem[];
    const uint32_t sbase = smem_u32_of(smem);
    float* v1s = smem + TAIL_F;   // 24
    float* v2s = v1s + 24;        // 24
    float* v3s = v2s + 24;        // 8

    const int t = threadIdx.x;
    const int wi = t >> 5, l = t & 31;
    const int ob = blockIdx.x * OB;
    const int by = blockIdx.y;

    const float* Kw = K + ((size_t)ob * I_DIM + by * IB + wi * WIB) * 9;
    const size_t ostr = (size_t)I_DIM * 9;
    const int i0 = by * IB + wi * WIB + l * 4;
    float* bufw = smem + wi * 2 * WSTAGE_FLOATS;
    const uint32_t bufw_a = sbase + wi * 2 * WSTAGE_BYTES;
    const uint32_t mb0 = sbase + MBAR_OFF + wi * 16;
    const uint32_t mb1 = mb0 + 8;

    if (t < OB * 3) { v1s[t] = g_v1[ob * 3 + t]; v2s[t] = g_v2[ob * 3 + t]; }
    if (t < OB) v3s[t] = g_v3[ob + t];
    if (t == 0) {
#pragma unroll
        for (int b = 0; b < 2 * NWARP; b++) mbar_init(sbase + MBAR_OFF + b * 8, 1);
        fence_async();
    }
    __syncthreads();
    if (l == 0) {  // prefetch o-rows OB-1, OB-2 (reverse traversal)
        mbar_expect_tx(mb0, WSTAGE_BYTES);
        bulk_g2s(bufw_a, Kw + (size_t)(OB - 1) * ostr, WSTAGE_BYTES, mb0);
        mbar_expect_tx(mb1, WSTAGE_BYTES);
        bulk_g2s(bufw_a + WSTAGE_BYTES, Kw + (size_t)(OB - 2) * ostr,
                 WSTAGE_BYTES, mb1);
    }

    u64t v42[2];
    {
        float4 v = *(const float4*)(g_v4 + i0);
        v42[0] = pk2(v.x, v.y);
        v42[1] = pk2(v.z, v.w);
    }

    u64t u1p2[6], u2p2[6], u3p2[18];
#pragma unroll
    for (int j = 0; j < 6; j++) { u1p2[j] = 0ull; u2p2[j] = 0ull; }
#pragma unroll
    for (int j = 0; j < 18; j++) u3p2[j] = 0ull;

#pragma unroll 1
    for (int s = 0; s < OB; s++) {
        const int ss = OB - 1 - s;  // reversed o-row index
        mbar_wait((s & 1) ? mb1 : mb0, (s >> 1) & 1);

        const float* kb = bufw + (s & 1) * WSTAGE_FLOATS + l * 36;
        float kk[36];
#pragma unroll
        for (int q = 0; q < 9; q++) ld4(kk + q * 4, kb + q * 4);

        u64t b1d[3], b2d[3], b3d;
#pragma unroll
        for (int j = 0; j < 3; j++) {
            const float b1 = v1s[ss * 3 + j]; b1d[j] = pk2(b1, b1);
            const float b2 = v2s[ss * 3 + j]; b2d[j] = pk2(b2, b2);
        }
        { const float b3 = v3s[ss]; b3d = pk2(b3, b3); }

        u64t u4a[9];
#pragma unroll
        for (int p = 0; p < 9; p++) u4a[p] = 0ull;

#pragma unroll
        for (int pi = 0; pi < 2; pi++) {
#pragma unroll
            for (int p = 0; p < 9; p++) {
                const int h = p / 3, w = p - h * 3;
                const u64t kp = pk2(kk[pi * 18 + p], kk[pi * 18 + 9 + p]);
                fma2(u1p2[pi * 3 + w], kp, b1d[h]);
                fma2(u2p2[pi * 3 + h], kp, b2d[w]);
                fma2(u3p2[pi * 9 + p], kp, b3d);
                fma2(u4a[p], kp, v42[pi]);
            }
        }

#pragma unroll
        for (int p = 0; p < 9; p++) {
            float2 f = upk(u4a[p]);
            float v = f.x + f.y;
#pragma unroll
            for (int sh = 16; sh > 0; sh >>= 1)
                v += __shfl_xor_sync(0xffffffffu, v, sh);
            if (l == 0) atomicAdd(&g_u4[(ob + ss) * 9 + p], v);
        }

        if (l == 0 && s + 2 < OB) {
            const uint32_t mb = (s & 1) ? mb1 : mb0;
            mbar_expect_tx(mb, WSTAGE_BYTES);
            bulk_g2s(bufw_a + (s & 1) * WSTAGE_BYTES,
                     Kw + (size_t)(OB - 1 - (s + 2)) * ostr, WSTAGE_BYTES, mb);
        }
    }

    // deterministic partials for u1/u2/u3 into scratch[go][*]
    float* scr = g_scr + (size_t)blockIdx.x * SCR_STRIDE;
    {
        float o1[12], o2[12];
#pragma unroll
        for (int pi = 0; pi < 2; pi++)
#pragma unroll
            for (int w = 0; w < 3; w++) {
                float2 f1 = upk(u1p2[pi * 3 + w]);
                o1[pi * 6 + w] = f1.x; o1[pi * 6 + 3 + w] = f1.y;
                float2 f2 = upk(u2p2[pi * 3 + w]);
                o2[pi * 6 + w] = f2.x; o2[pi * 6 + 3 + w] = f2.y;
            }
#pragma unroll
        for (int q = 0; q < 3; q++) {
            *(float4*)(scr + i0 * 3 + q * 4) =
                make_float4(o1[q * 4], o1[q * 4 + 1], o1[q * 4 + 2], o1[q * 4 + 3]);
            *(float4*)(scr + 6144 + i0 * 3 + q * 4) =
                make_float4(o2[q * 4], o2[q * 4 + 1], o2[q * 4 + 2], o2[q * 4 + 3]);
        }
        float o3[36];
#pragma unroll
        for (int pi = 0; pi < 2; pi++)
#pragma unroll
            for (int p = 0; p < 9; p++) {
                float2 f = upk(u3p2[pi * 9 + p]);
                o3[pi * 18 + p] = f.x; o3[pi * 18 + 9 + p] = f.y;
            }
#pragma unroll
        for (int q = 0; q < 9; q++)
            *(float4*)(scr + 12288 + i0 * 9 + q * 4) =
                make_float4(o3[q * 4], o3[q * 4 + 1], o3[q * 4 + 2], o3[q * 4 + 3]);
    }
}

// ---- U-pass stage 2: reduce partials, write u, ||w||^2, zero v for next ----
__global__ void ustage2_kernel(int zero_vss) {
    const int b = blockIdx.x, t = threadIdx.x;  // grid 54 x 1024
    if (b < 48) {
        const int e = b * 1024 + t;
        float val;
        int mode;
        if (e < U_ELEMS) {
            float s = 0.f;
#pragma unroll 8
            for (int g = 0; g < GO; g++) s += g_scr[(size_t)g * SCR_STRIDE + e];
            if (b < 6)       { g_u1[e] = s;          mode = 0; }
            else if (b < 12) { g_u2[e - 6144] = s;   mode = 1; }
            else             { g_u3[e - 12288] = s;  mode = 2; }
            val = s;
        } else {
            val = g_u4[e - U_ELEMS];
            mode = 3;
        }
        float tot = block_sum1024(val * val);
        if (t == 0) atomicAdd(&g_wss[mode], tot);
    } else {
        const int e = (b - 48) * 1024 + t;  // 0..6143
        g_v1[e] = 0.f; g_v2[e] = 0.f;
        if (e < O_DIM) { g_v3[e] = 0.f; g_v4[e] = 0.f; }
        if (zero_vss && b == 48 && t < 4) g_vss[t] = 0.f;
    }
}

// ---------------- final: out = K / min_m sigma_m ---------------------------
// Mirrored block index: starts where the final (reverse) upass finished.
__global__ void scale_kernel(const float* __restrict__ K, float* __restrict__ out) {
    float s2min = g_wss[0] / g_vss[0];
#pragma unroll
    for (int m = 1; m < 4; m++) {
        float s2 = g_wss[m] / g_vss[m];
        s2min = fminf(s2min, s2);
    }
    const float inv = rsqrtf(s2min);  // 1/sigma
    const size_t blk = (size_t)(gridDim.x - 1 - blockIdx.x);
    const size_t idx = blk * 1024 + threadIdx.x;
    float4 v = ((const float4*)K)[idx];
    v.x *= inv; v.y *= inv; v.z *= inv; v.w *= inv;
    ((float4*)out)[idx] = v;
}

// ---------------- launch ----------------
extern "C" void kernel_launch(void* const* d_in, const int* in_sizes, int n_in,
                              void* d_out, int out_size) {
    const float* K  = (const float*)d_in[0];
    const float* u1 = (const float*)d_in[1];
    const float* u2 = (const float*)d_in[2];
    const float* u3 = (const float*)d_in[3];
    const float* u4 = (const float*)d_in[4];
    float* out = (float*)d_out;

    dim3 pg(GO, GI);
    zero_v_kernel<<<6, 1024>>>();
    for (int it = 0; it < 3; it++) {
        vpass_kernel<<<pg, TB, SMEM_DYN>>>(K, u1, u2, u3, u4, it == 0 ? 1 : 0);
        vnorm_zero_kernel<<<34, 1024>>>();            // v sumsq + zero u4/wss
        upass_kernel<<<pg, TB, SMEM_DYN>>>(K);
        ustage2_kernel<<<54, 1024>>>(it < 2 ? 1 : 0); // u reduce + w sumsq + zero v
    }
    scale_kernel<<<(O_DIM * I_DIM * 9) / 4096, 1024>>>(K, out);
}

// round 13
// speedup vs baseline: 1.0813x; 1.0813x over previous
#include <cuda_runtime.h>
#include <math.h>
#include <cstdint>

#define O_DIM 2048
#define I_DIM 2048
#define OB 16
#define GO (O_DIM / OB)      // 128 o-chunks
#define GI 4                 // i split
#define IB (I_DIM / GI)      // 512 i-rows per block
#define TB 128               // 4 warps; each warp owns 128 i-rows
#define NWARP 4
#define WIB 128              // i-rows per warp
#define NB 3                 // warp-private ring depth
#define WSTAGE_FLOATS (WIB * 9)          // 1152 floats per warp-stage
#define WSTAGE_BYTES (WSTAGE_FLOATS * 4) // 4608 bytes
#define MBAR_OFF (NWARP * NB * WSTAGE_BYTES)  // 55296
#define TAIL_F (MBAR_OFF / 4 + 32)            // float idx past mbars (128B pad)
#define SMEM_DYN ((TAIL_F + 160) * 4)
#define U_ELEMS 30720        // |u1|+|u2|+|u3| = 6144+6144+18432
#define SCR_STRIDE 30720

typedef unsigned long long u64t;

// ---------------- persistent device state (static, no allocation) ----------
__device__ __align__(16) float g_v1[O_DIM * 3];
__device__ __align__(16) float g_v2[O_DIM * 3];
__device__ __align__(16) float g_v3[O_DIM];
__device__ __align__(16) float g_v4[I_DIM];
__device__ __align__(16) float g_u1[I_DIM * 3];
__device__ __align__(16) float g_u2[I_DIM * 3];
__device__ __align__(16) float g_u3[I_DIM * 9];
__device__ __align__(16) float g_u4[O_DIM * 9];
__device__ __align__(16) float g_scr[(size_t)GO * SCR_STRIDE];  // u123 partials
__device__ float g_vss[4];  // ||v_m||^2 (final iter)
__device__ float g_wss[4];  // ||w_m||^2 (final iter)

// ---------------- helpers ----------------
__device__ __forceinline__ uint32_t smem_u32_of(const void* p) {
    uint32_t a;
    asm("{ .reg .u64 t; cvta.to.shared.u64 t, %1; cvt.u32.u64 %0, t; }"
        : "=r"(a) : "l"(p));
    return a;
}
__device__ __forceinline__ void mbar_init(uint32_t mbar, uint32_t cnt) {
    asm volatile("mbarrier.init.shared.b64 [%0], %1;" :: "r"(mbar), "r"(cnt) : "memory");
}
__device__ __forceinline__ void mbar_expect_tx(uint32_t mbar, uint32_t bytes) {
    asm volatile("mbarrier.arrive.expect_tx.shared.b64 _, [%0], %1;"
                 :: "r"(mbar), "r"(bytes) : "memory");
}
__device__ __forceinline__ void mbar_wait(uint32_t mbar, uint32_t parity) {
    asm volatile(
        "{\n\t"
        ".reg .pred P1;\n\t"
        "W_%=:\n\t"
        "mbarrier.try_wait.parity.acquire.cta.shared::cta.b64 P1, [%0], %1, 0x989680;\n\t"
        "@P1 bra D_%=;\n\t"
        "bra W_%=;\n\t"
        "D_%=:\n\t"
        "}"
        :: "r"(mbar), "r"(parity) : "memory");
}
__device__ __forceinline__ void bulk_g2s(uint32_t dst, const void* src,
                                         uint32_t bytes, uint32_t mbar) {
    asm volatile(
        "cp.async.bulk.shared::cta.global.mbarrier::complete_tx::bytes [%0], [%1], %2, [%3];"
        :: "r"(dst), "l"(src), "r"(bytes), "r"(mbar) : "memory");
}
__device__ __forceinline__ void fence_async() {
    asm volatile("fence.proxy.async.shared::cta;" ::: "memory");
}

// packed fp32x2
__device__ __forceinline__ void fma2(u64t& d, u64t a, u64t b) {
    asm("fma.rn.f32x2 %0, %1, %2, %0;" : "+l"(d) : "l"(a), "l"(b));
}
__device__ __forceinline__ u64t pk2(float lo, float hi) {
    u64t r; asm("mov.b64 %0, {%1, %2};" : "=l"(r) : "f"(lo), "f"(hi)); return r;
}
__device__ __forceinline__ float2 upk(u64t v) {
    float2 r; asm("mov.b64 {%0, %1}, %2;" : "=f"(r.x), "=f"(r.y) : "l"(v)); return r;
}

__device__ __forceinline__ float block_sum1024(float v) {
    __shared__ float sred[32];
#pragma unroll
    for (int s = 16; s > 0; s >>= 1) v += __shfl_xor_sync(0xffffffffu, v, s);
    if ((threadIdx.x & 31) == 0) sred[threadIdx.x >> 5] = v;
    __syncthreads();
    if (threadIdx.x < 32) {
        v = sred[threadIdx.x];
#pragma unroll
        for (int s = 16; s > 0; s >>= 1) v += __shfl_xor_sync(0xffffffffu, v, s);
    }
    return v;  // valid on thread 0
}

__device__ __forceinline__ void ld4(float* dst, const float* src) {
    float4 a = *(const float4*)src;
    dst[0] = a.x; dst[1] = a.y; dst[2] = a.z; dst[3] = a.w;
}

// ---------------- tiny kernels ----------------
__global__ void zero_v_kernel() {
    int idx = blockIdx.x * 1024 + threadIdx.x;  // grid 6 x 1024 = 6144
    if (idx < O_DIM * 3) { g_v1[idx] = 0.f; g_v2[idx] = 0.f; }
    if (idx < O_DIM)     { g_v3[idx] = 0.f; g_v4[idx] = 0.f; }
    if (idx < 4)         g_vss[idx] = 0.f;
}

// blocks 0..15: sumsq of v's into g_vss ; blocks 16..33: zero g_u4 (+g_wss)
__global__ void vnorm_zero_kernel() {
    const int b = blockIdx.x, t = threadIdx.x;
    if (b < 16) {
        const int e = b * 1024 + t;
        float val;
        int mode;
        if (b < 6)       { val = g_v1[e];          mode = 0; }
        else if (b < 12) { val = g_v2[e - 6144];   mode = 1; }
        else if (b < 14) { val = g_v3[e - 12288];  mode = 2; }
        else             { val = g_v4[e - 14336];  mode = 3; }
        float tot = block_sum1024(val * val);
        if (t == 0) atomicAdd(&g_vss[mode], tot);
    } else {
        const int e = (b - 16) * 1024 + t;
        if (e < O_DIM * 9) g_u4[e] = 0.f;
        if (b == 16 && t < 4) g_wss[t] = 0.f;
    }
}

// ---------------- V-pass: v = contract(K, u) for all 4 modes ----------------
// Warp w owns i-rows [128w,128w+128) with a PRIVATE 3-deep TMA ring
// (2 refills in flight). FORWARD o traversal (upass runs REVERSE: L2 ping-pong).
__global__ void __launch_bounds__(TB) vpass_kernel(
    const float* __restrict__ K,
    const float* eu1, const float* eu2, const float* eu3, const float* eu4,
    int use_ext) {
    extern __shared__ __align__(16) float smem[];
    const uint32_t sbase = smem_u32_of(smem);
    float* u4s = smem + TAIL_F;  // 144 floats

    const float* u1 = use_ext ? eu1 : g_u1;
    const float* u2 = use_ext ? eu2 : g_u2;
    const float* u3 = use_ext ? eu3 : g_u3;
    const float* u4 = use_ext ? eu4 : g_u4;

    const int t = threadIdx.x;
    const int wi = t >> 5, l = t & 31;
    const int ob = blockIdx.x * OB;
    const int by = blockIdx.y;

    const float* Kw = K + ((size_t)ob * I_DIM + by * IB + wi * WIB) * 9;
    const size_t ostr = (size_t)I_DIM * 9;
    const int i0 = by * IB + wi * WIB + l * 4;  // 4 consecutive i-rows
    float* bufw = smem + wi * NB * WSTAGE_FLOATS;
    const uint32_t bufw_a = sbase + wi * NB * WSTAGE_BYTES;
    const uint32_t mbw = sbase + MBAR_OFF + wi * NB * 8;

    for (int j = t; j < OB * 9; j += TB) u4s[j] = u4[ob * 9 + j];
    if (t == 0) {
#pragma unroll
        for (int b = 0; b < NWARP * NB; b++) mbar_init(sbase + MBAR_OFF + b * 8, 1);
        fence_async();
    }
    __syncthreads();
    if (l == 0) {  // each warp's lane0 drives its own pipeline: stages 0,1,2
#pragma unroll
        for (int s = 0; s < NB; s++) {
            mbar_expect_tx(mbw + s * 8, WSTAGE_BYTES);
            bulk_g2s(bufw_a + s * WSTAGE_BYTES, Kw + (size_t)s * ostr,
                     WSTAGE_BYTES, mbw + s * 8);
        }
    }

    // pack u operands along (row, row+1) pairs
    u64t u1pr[6], u2pr[6], u3pr[18];
    {
        float a[12], b[12], c3[36];
#pragma unroll
        for (int q = 0; q < 3; q++) ld4(a + q * 4, u1 + i0 * 3 + q * 4);
#pragma unroll
        for (int q = 0; q < 3; q++) ld4(b + q * 4, u2 + i0 * 3 + q * 4);
#pragma unroll
        for (int q = 0; q < 9; q++) ld4(c3 + q * 4, u3 + i0 * 9 + q * 4);
#pragma unroll
        for (int pi = 0; pi < 2; pi++) {
#pragma unroll
            for (int w = 0; w < 3; w++) {
                u1pr[pi * 3 + w] = pk2(a[pi * 6 + w], a[pi * 6 + 3 + w]);
                u2pr[pi * 3 + w] = pk2(b[pi * 6 + w], b[pi * 6 + 3 + w]);
            }
#pragma unroll
            for (int p = 0; p < 9; p++)
                u3pr[pi * 9 + p] = pk2(c3[pi * 18 + p], c3[pi * 18 + 9 + p]);
        }
    }

    u64t v4acc[2] = {0ull, 0ull};

#pragma unroll 1
    for (int s = 0; s < OB; s++) {
        const int bi = s - (s / NB) * NB;        // s % 3
        const int par = (s / NB) & 1;
        mbar_wait(mbw + bi * 8, par);

        const float* kb = bufw + bi * WSTAGE_FLOATS + l * 36;
        float kk[36];
#pragma unroll
        for (int q = 0; q < 9; q++) ld4(kk + q * 4, kb + q * 4);

        u64t cd[9];
#pragma unroll
        for (int p = 0; p < 9; p++) {
            const float c = u4s[s * 9 + p];
            cd[p] = pk2(c, c);
        }

        u64t acc1[3] = {0ull, 0ull, 0ull};
        u64t acc2[3] = {0ull, 0ull, 0ull};
        u64t acc3 = 0ull;
#pragma unroll
        for (int pi = 0; pi < 2; pi++) {
#pragma unroll
            for (int p = 0; p < 9; p++) {
                const int h = p / 3, w = p - h * 3;
                const u64t kp = pk2(kk[pi * 18 + p], kk[pi * 18 + 9 + p]);
                fma2(acc1[h], kp, u1pr[pi * 3 + w]);
                fma2(acc2[w], kp, u2pr[pi * 3 + h]);
                fma2(acc3, kp, u3pr[pi * 9 + p]);
                fma2(v4acc[pi], kp, cd[p]);
            }
        }

        float r[7];
#pragma unroll
        for (int j = 0; j < 3; j++) {
            float2 f1 = upk(acc1[j]); r[j] = f1.x + f1.y;
            float2 f2 = upk(acc2[j]); r[3 + j] = f2.x + f2.y;
        }
        { float2 f3 = upk(acc3); r[6] = f3.x + f3.y; }
#pragma unroll
        for (int j = 0; j < 7; j++)
#pragma unroll
            for (int sh = 16; sh > 0; sh >>= 1)
                r[j] += __shfl_xor_sync(0xffffffffu, r[j], sh);
        if (l == 0) {
            const int o = ob + s;
            atomicAdd(&g_v1[o * 3 + 0], r[0]);
            atomicAdd(&g_v1[o * 3 + 1], r[1]);
            atomicAdd(&g_v1[o * 3 + 2], r[2]);
            atomicAdd(&g_v2[o * 3 + 0], r[3]);
            atomicAdd(&g_v2[o * 3 + 1], r[4]);
            atomicAdd(&g_v2[o * 3 + 2], r[5]);
            atomicAdd(&g_v3[o], r[6]);
            // refill just-consumed buffer with stage s+NB (warp-private:
            // all lanes' LDS of this buffer precede this via the shfl chain)
            if (s + NB < OB) {
                mbar_expect_tx(mbw + bi * 8, WSTAGE_BYTES);
                bulk_g2s(bufw_a + bi * WSTAGE_BYTES,
                         Kw + (size_t)(s + NB) * ostr, WSTAGE_BYTES,
                         mbw + bi * 8);
            }
        }
    }

    float2 fa = upk(v4acc[0]), fb = upk(v4acc[1]);
    atomicAdd(&g_v4[i0 + 0], fa.x);
    atomicAdd(&g_v4[i0 + 1], fa.y);
    atomicAdd(&g_v4[i0 + 2], fb.x);
    atomicAdd(&g_v4[i0 + 3], fb.y);
}

// ------- U-pass stage 1: w = contract(K, v), REVERSE o traversal -----------
// Reads the o-rows the preceding vpass touched LAST, first -> L2 ping-pong.
__global__ void __launch_bounds__(TB) upass_kernel(const float* __restrict__ K) {
    extern __shared__ __align__(16) float smem[];
    const uint32_t sbase = smem_u32_of(smem);
    float* v1s = smem + TAIL_F;   // 48
    float* v2s = v1s + 48;        // 48
    float* v3s = v2s + 48;        // 16

    const int t = threadIdx.x;
    const int wi = t >> 5, l = t & 31;
    const int ob = blockIdx.x * OB;
    const int by = blockIdx.y;

    const float* Kw = K + ((size_t)ob * I_DIM + by * IB + wi * WIB) * 9;
    const size_t ostr = (size_t)I_DIM * 9;
    const int i0 = by * IB + wi * WIB + l * 4;
    float* bufw = smem + wi * NB * WSTAGE_FLOATS;
    const uint32_t bufw_a = sbase + wi * NB * WSTAGE_BYTES;
    const uint32_t mbw = sbase + MBAR_OFF + wi * NB * 8;

    if (t < 48) { v1s[t] = g_v1[ob * 3 + t]; v2s[t] = g_v2[ob * 3 + t]; }
    if (t < 16) v3s[t] = g_v3[ob + t];
    if (t == 0) {
#pragma unroll
        for (int b = 0; b < NWARP * NB; b++) mbar_init(sbase + MBAR_OFF + b * 8, 1);
        fence_async();
    }
    __syncthreads();
    if (l == 0) {  // prefetch o-rows OB-1, OB-2, OB-3 (reverse traversal)
#pragma unroll
        for (int s = 0; s < NB; s++) {
            mbar_expect_tx(mbw + s * 8, WSTAGE_BYTES);
            bulk_g2s(bufw_a + s * WSTAGE_BYTES,
                     Kw + (size_t)(OB - 1 - s) * ostr, WSTAGE_BYTES, mbw + s * 8);
        }
    }

    u64t v42[2];
    {
        float4 v = *(const float4*)(g_v4 + i0);
        v42[0] = pk2(v.x, v.y);
        v42[1] = pk2(v.z, v.w);
    }

    u64t u1p2[6], u2p2[6], u3p2[18];
#pragma unroll
    for (int j = 0; j < 6; j++) { u1p2[j] = 0ull; u2p2[j] = 0ull; }
#pragma unroll
    for (int j = 0; j < 18; j++) u3p2[j] = 0ull;

#pragma unroll 1
    for (int s = 0; s < OB; s++) {
        const int ss = OB - 1 - s;  // reversed o-row index
        const int bi = s - (s / NB) * NB;
        const int par = (s / NB) & 1;
        mbar_wait(mbw + bi * 8, par);

        const float* kb = bufw + bi * WSTAGE_FLOATS + l * 36;
        float kk[36];
#pragma unroll
        for (int q = 0; q < 9; q++) ld4(kk + q * 4, kb + q * 4);

        u64t b1d[3], b2d[3], b3d;
#pragma unroll
        for (int j = 0; j < 3; j++) {
            const float b1 = v1s[ss * 3 + j]; b1d[j] = pk2(b1, b1);
            const float b2 = v2s[ss * 3 + j]; b2d[j] = pk2(b2, b2);
        }
        { const float b3 = v3s[ss]; b3d = pk2(b3, b3); }

        u64t u4a[9];
#pragma unroll
        for (int p = 0; p < 9; p++) u4a[p] = 0ull;

#pragma unroll
        for (int pi = 0; pi < 2; pi++) {
#pragma unroll
            for (int p = 0; p < 9; p++) {
                const int h = p / 3, w = p - h * 3;
                const u64t kp = pk2(kk[pi * 18 + p], kk[pi * 18 + 9 + p]);
                fma2(u1p2[pi * 3 + w], kp, b1d[h]);
                fma2(u2p2[pi * 3 + h], kp, b2d[w]);
                fma2(u3p2[pi * 9 + p], kp, b3d);
                fma2(u4a[p], kp, v42[pi]);
            }
        }

#pragma unroll
        for (int p = 0; p < 9; p++) {
            float2 f = upk(u4a[p]);
            float v = f.x + f.y;
#pragma unroll
            for (int sh = 16; sh > 0; sh >>= 1)
                v += __shfl_xor_sync(0xffffffffu, v, sh);
            if (l == 0) atomicAdd(&g_u4[(ob + ss) * 9 + p], v);
        }

        if (l == 0 && s + NB < OB) {
            mbar_expect_tx(mbw + bi * 8, WSTAGE_BYTES);
            bulk_g2s(bufw_a + bi * WSTAGE_BYTES,
                     Kw + (size_t)(OB - 1 - (s + NB)) * ostr, WSTAGE_BYTES,
                     mbw + bi * 8);
        }
    }

    // deterministic partials for u1/u2/u3 into scratch[go][*]
    float* scr = g_scr + (size_t)blockIdx.x * SCR_STRIDE;
    {
        float o1[12], o2[12];
#pragma unroll
        for (int pi = 0; pi < 2; pi++)
#pragma unroll
            for (int w = 0; w < 3; w++) {
                float2 f1 = upk(u1p2[pi * 3 + w]);
                o1[pi * 6 + w] = f1.x; o1[pi * 6 + 3 + w] = f1.y;
                float2 f2 = upk(u2p2[pi * 3 + w]);
                o2[pi * 6 + w] = f2.x; o2[pi * 6 + 3 + w] = f2.y;
            }
#pragma unroll
        for (int q = 0; q < 3; q++) {
            *(float4*)(scr + i0 * 3 + q * 4) =
                make_float4(o1[q * 4], o1[q * 4 + 1], o1[q * 4 + 2], o1[q * 4 + 3]);
            *(float4*)(scr + 6144 + i0 * 3 + q * 4) =
                make_float4(o2[q * 4], o2[q * 4 + 1], o2[q * 4 + 2], o2[q * 4 + 3]);
        }
        float o3[36];
#pragma unroll
        for (int pi = 0; pi < 2; pi++)
#pragma unroll
            for (int p = 0; p < 9; p++) {
                float2 f = upk(u3p2[pi * 9 + p]);
                o3[pi * 18 + p] = f.x; o3[pi * 18 + 9 + p] = f.y;
            }
#pragma unroll
        for (int q = 0; q < 9; q++)
            *(float4*)(scr + 12288 + i0 * 9 + q * 4) =
                make_float4(o3[q * 4], o3[q * 4 + 1], o3[q * 4 + 2], o3[q * 4 + 3]);
    }
}

// ---- U-pass stage 2: reduce partials, write u, ||w||^2, zero v for next ----
__global__ void ustage2_kernel(int zero_vss) {
    const int b = blockIdx.x, t = threadIdx.x;  // grid 54 x 1024
    if (b < 48) {
        const int e = b * 1024 + t;
        float val;
        int mode;
        if (e < U_ELEMS) {
            float s = 0.f;
#pragma unroll 8
            for (int g = 0; g < GO; g++) s += g_scr[(size_t)g * SCR_STRIDE + e];
            if (b < 6)       { g_u1[e] = s;          mode = 0; }
            else if (b < 12) { g_u2[e - 6144] = s;   mode = 1; }
            else             { g_u3[e - 12288] = s;  mode = 2; }
            val = s;
        } else {
            val = g_u4[e - U_ELEMS];
            mode = 3;
        }
        float tot = block_sum1024(val * val);
        if (t == 0) atomicAdd(&g_wss[mode], tot);
    } else {
        const int e = (b - 48) * 1024 + t;  // 0..6143
        g_v1[e] = 0.f; g_v2[e] = 0.f;
        if (e < O_DIM) { g_v3[e] = 0.f; g_v4[e] = 0.f; }
        if (zero_vss && b == 48 && t < 4) g_vss[t] = 0.f;
    }
}

// ---------------- final: out = K / min_m sigma_m ---------------------------
// Mirrored block index: starts where the final (reverse) upass finished.
__global__ void scale_kernel(const float* __restrict__ K, float* __restrict__ out) {
    float s2min = g_wss[0] / g_vss[0];
#pragma unroll
    for (int m = 1; m < 4; m++) {
        float s2 = g_wss[m] / g_vss[m];
        s2min = fminf(s2min, s2);
    }
    const float inv = rsqrtf(s2min);  // 1/sigma
    const size_t blk = (size_t)(gridDim.x - 1 - blockIdx.x);
    const size_t idx = blk * 1024 + threadIdx.x;
    float4 v = ((const float4*)K)[idx];
    v.x *= inv; v.y *= inv; v.z *= inv; v.w *= inv;
    ((float4*)out)[idx] = v;
}

// ---------------- launch ----------------
extern "C" void kernel_launch(void* const* d_in, const int* in_sizes, int n_in,
                              void* d_out, int out_size) {
    const float* K  = (const float*)d_in[0];
    const float* u1 = (const float*)d_in[1];
    const float* u2 = (const float*)d_in[2];
    const float* u3 = (const float*)d_in[3];
    const float* u4 = (const float*)d_in[4];
    float* out = (float*)d_out;

    static int attr_done = 0;
    if (!attr_done) {
        cudaFuncSetAttribute(vpass_kernel,
                             cudaFuncAttributeMaxDynamicSharedMemorySize, SMEM_DYN);
        cudaFuncSetAttribute(upass_kernel,
                             cudaFuncAttributeMaxDynamicSharedMemorySize, SMEM_DYN);
        attr_done = 1;
    }

    dim3 pg(GO, GI);
    zero_v_kernel<<<6, 1024>>>();
    for (int it = 0; it < 3; it++) {
        vpass_kernel<<<pg, TB, SMEM_DYN>>>(K, u1, u2, u3, u4, it == 0 ? 1 : 0);
        vnorm_zero_kernel<<<34, 1024>>>();            // v sumsq + zero u4/wss
        upass_kernel<<<pg, TB, SMEM_DYN>>>(K);
        ustage2_kernel<<<54, 1024>>>(it < 2 ? 1 : 0); // u reduce + w sumsq + zero v
    }
    scale_kernel<<<(O_DIM * I_DIM * 9) / 4096, 1024>>>(K, out);
}

// round 14
// speedup vs baseline: 1.3515x; 1.2498x over previous
#include <cuda_runtime.h>
#include <math.h>
#include <cstdint>

#define O_DIM 2048
#define I_DIM 2048
#define OB 16
#define GO (O_DIM / OB)      // 128 o-chunks
#define GI 4                 // i split
#define IB (I_DIM / GI)      // 512 i-rows per block
#define TB 128               // 4 warps; each warp owns 128 i-rows
#define NWARP 4
#define WIB 128              // i-rows per warp
#define NB 3                 // warp-private ring depth (2 refills in flight)
#define WSTAGE_FLOATS (WIB * 9)          // 1152 floats per warp-stage
#define WSTAGE_BYTES (WSTAGE_FLOATS * 4) // 4608 bytes
#define MBAR_OFF (NWARP * NB * WSTAGE_BYTES)  // 55296
#define TAIL_F (MBAR_OFF / 4 + 32)            // float idx past mbars (128B pad)
#define SMEM_DYN ((TAIL_F + 160) * 4)
#define U_ELEMS 30720        // |u1|+|u2|+|u3| = 6144+6144+18432
#define SCR_STRIDE 30720

typedef unsigned long long u64t;

// ---------------- persistent device state (static, no allocation) ----------
__device__ __align__(16) float g_v1[O_DIM * 3];
__device__ __align__(16) float g_v2[O_DIM * 3];
__device__ __align__(16) float g_v3[O_DIM];
__device__ __align__(16) float g_v4[I_DIM];
__device__ __align__(16) float g_u1[I_DIM * 3];
__device__ __align__(16) float g_u2[I_DIM * 3];
__device__ __align__(16) float g_u3[I_DIM * 9];
__device__ __align__(16) float g_u4[O_DIM * 9];
__device__ __align__(16) float g_scr[(size_t)GO * SCR_STRIDE];  // u123 partials
__device__ float g_vss[4];  // ||v_m||^2 (final iter)
__device__ float g_wss[4];  // ||w_m||^2 (final iter)

// ---------------- helpers ----------------
__device__ __forceinline__ uint32_t smem_u32_of(const void* p) {
    uint32_t a;
    asm("{ .reg .u64 t; cvta.to.shared.u64 t, %1; cvt.u32.u64 %0, t; }"
        : "=r"(a) : "l"(p));
    return a;
}
__device__ __forceinline__ void mbar_init(uint32_t mbar, uint32_t cnt) {
    asm volatile("mbarrier.init.shared.b64 [%0], %1;" :: "r"(mbar), "r"(cnt) : "memory");
}
__device__ __forceinline__ void mbar_expect_tx(uint32_t mbar, uint32_t bytes) {
    asm volatile("mbarrier.arrive.expect_tx.shared.b64 _, [%0], %1;"
                 :: "r"(mbar), "r"(bytes) : "memory");
}
__device__ __forceinline__ void mbar_wait(uint32_t mbar, uint32_t parity) {
    asm volatile(
        "{\n\t"
        ".reg .pred P1;\n\t"
        "W_%=:\n\t"
        "mbarrier.try_wait.parity.acquire.cta.shared::cta.b64 P1, [%0], %1, 0x989680;\n\t"
        "@P1 bra D_%=;\n\t"
        "bra W_%=;\n\t"
        "D_%=:\n\t"
        "}"
        :: "r"(mbar), "r"(parity) : "memory");
}
__device__ __forceinline__ void bulk_g2s(uint32_t dst, const void* src,
                                         uint32_t bytes, uint32_t mbar) {
    asm volatile(
        "cp.async.bulk.shared::cta.global.mbarrier::complete_tx::bytes [%0], [%1], %2, [%3];"
        :: "r"(dst), "l"(src), "r"(bytes), "r"(mbar) : "memory");
}
__device__ __forceinline__ void fence_async() {
    asm volatile("fence.proxy.async.shared::cta;" ::: "memory");
}

// packed fp32x2
__device__ __forceinline__ void fma2(u64t& d, u64t a, u64t b) {
    asm("fma.rn.f32x2 %0, %1, %2, %0;" : "+l"(d) : "l"(a), "l"(b));
}
__device__ __forceinline__ u64t pk2(float lo, float hi) {
    u64t r; asm("mov.b64 %0, {%1, %2};" : "=l"(r) : "f"(lo), "f"(hi)); return r;
}
__device__ __forceinline__ float2 upk(u64t v) {
    float2 r; asm("mov.b64 {%0, %1}, %2;" : "=f"(r.x), "=f"(r.y) : "l"(v)); return r;
}

__device__ __forceinline__ float block_sum1024(float v) {
    __shared__ float sred[32];
#pragma unroll
    for (int s = 16; s > 0; s >>= 1) v += __shfl_xor_sync(0xffffffffu, v, s);
    if ((threadIdx.x & 31) == 0) sred[threadIdx.x >> 5] = v;
    __syncthreads();
    if (threadIdx.x < 32) {
        v = sred[threadIdx.x];
#pragma unroll
        for (int s = 16; s > 0; s >>= 1) v += __shfl_xor_sync(0xffffffffu, v, s);
    }
    return v;  // valid on thread 0
}

__device__ __forceinline__ void ld4(float* dst, const float* src) {
    float4 a = *(const float4*)src;
    dst[0] = a.x; dst[1] = a.y; dst[2] = a.z; dst[3] = a.w;
}

// ---------------- tiny kernels ----------------
__global__ void zero_v_kernel() {
    int idx = blockIdx.x * 1024 + threadIdx.x;  // grid 6 x 1024 = 6144
    if (idx < O_DIM * 3) { g_v1[idx] = 0.f; g_v2[idx] = 0.f; }
    if (idx < O_DIM)     { g_v3[idx] = 0.f; g_v4[idx] = 0.f; }
    if (idx < 4)         g_vss[idx] = 0.f;
}

// blocks 0..15: sumsq of v's into g_vss ; blocks 16..33: zero g_u4 (+g_wss)
__global__ void vnorm_zero_kernel() {
    const int b = blockIdx.x, t = threadIdx.x;
    if (b < 16) {
        const int e = b * 1024 + t;
        float val;
        int mode;
        if (b < 6)       { val = g_v1[e];          mode = 0; }
        else if (b < 12) { val = g_v2[e - 6144];   mode = 1; }
        else if (b < 14) { val = g_v3[e - 12288];  mode = 2; }
        else             { val = g_v4[e - 14336];  mode = 3; }
        float tot = block_sum1024(val * val);
        if (t == 0) atomicAdd(&g_vss[mode], tot);
    } else {
        const int e = (b - 16) * 1024 + t;
        if (e < O_DIM * 9) g_u4[e] = 0.f;
        if (b == 16 && t < 4) g_wss[t] = 0.f;
    }
}

// ---------------- V-pass: v = contract(K, u) for all 4 modes ----------------
// Warp w owns i-rows [128w,128w+128) with a PRIVATE 3-deep TMA ring
// (2 refills in flight). FORWARD o traversal (upass runs REVERSE: L2 ping-pong).
__global__ void __launch_bounds__(TB, 4) vpass_kernel(
    const float* __restrict__ K,
    const float* eu1, const float* eu2, const float* eu3, const float* eu4,
    int use_ext) {
    extern __shared__ __align__(16) float smem[];
    const uint32_t sbase = smem_u32_of(smem);
    float* u4s = smem + TAIL_F;  // 144 floats

    const float* u1 = use_ext ? eu1 : g_u1;
    const float* u2 = use_ext ? eu2 : g_u2;
    const float* u3 = use_ext ? eu3 : g_u3;
    const float* u4 = use_ext ? eu4 : g_u4;

    const int t = threadIdx.x;
    const int wi = t >> 5, l = t & 31;
    const int ob = blockIdx.x * OB;
    const int by = blockIdx.y;

    const float* Kw = K + ((size_t)ob * I_DIM + by * IB + wi * WIB) * 9;
    const size_t ostr = (size_t)I_DIM * 9;
    const int i0 = by * IB + wi * WIB + l * 4;  // 4 consecutive i-rows
    float* bufw = smem + wi * NB * WSTAGE_FLOATS;
    const uint32_t bufw_a = sbase + wi * NB * WSTAGE_BYTES;
    const uint32_t mbw = sbase + MBAR_OFF + wi * NB * 8;

    for (int j = t; j < OB * 9; j += TB) u4s[j] = u4[ob * 9 + j];
    if (t == 0) {
#pragma unroll
        for (int b = 0; b < NWARP * NB; b++) mbar_init(sbase + MBAR_OFF + b * 8, 1);
        fence_async();
    }
    __syncthreads();
    if (l == 0) {  // each warp's lane0 drives its own pipeline: stages 0,1,2
#pragma unroll
        for (int s = 0; s < NB; s++) {
            mbar_expect_tx(mbw + s * 8, WSTAGE_BYTES);
            bulk_g2s(bufw_a + s * WSTAGE_BYTES, Kw + (size_t)s * ostr,
                     WSTAGE_BYTES, mbw + s * 8);
        }
    }

    // pack u operands along (row, row+1) pairs
    u64t u1pr[6], u2pr[6], u3pr[18];
    {
        float a[12], b[12], c3[36];
#pragma unroll
        for (int q = 0; q < 3; q++) ld4(a + q * 4, u1 + i0 * 3 + q * 4);
#pragma unroll
        for (int q = 0; q < 3; q++) ld4(b + q * 4, u2 + i0 * 3 + q * 4);
#pragma unroll
        for (int q = 0; q < 9; q++) ld4(c3 + q * 4, u3 + i0 * 9 + q * 4);
#pragma unroll
        for (int pi = 0; pi < 2; pi++) {
#pragma unroll
            for (int w = 0; w < 3; w++) {
                u1pr[pi * 3 + w] = pk2(a[pi * 6 + w], a[pi * 6 + 3 + w]);
                u2pr[pi * 3 + w] = pk2(b[pi * 6 + w], b[pi * 6 + 3 + w]);
            }
#pragma unroll
            for (int p = 0; p < 9; p++)
                u3pr[pi * 9 + p] = pk2(c3[pi * 18 + p], c3[pi * 18 + 9 + p]);
        }
    }

    u64t v4acc[2] = {0ull, 0ull};

    int bi = 0, par = 0;  // rolling ring index + parity (no % ops)
#pragma unroll 1
    for (int s = 0; s < OB; s++) {
        mbar_wait(mbw + bi * 8, par);

        const float* kb = bufw + bi * WSTAGE_FLOATS + l * 36;
        float kk[36];
#pragma unroll
        for (int q = 0; q < 9; q++) ld4(kk + q * 4, kb + q * 4);

        u64t cd[9];
#pragma unroll
        for (int p = 0; p < 9; p++) {
            const float c = u4s[s * 9 + p];
            cd[p] = pk2(c, c);
        }

        u64t acc1[3] = {0ull, 0ull, 0ull};
        u64t acc2[3] = {0ull, 0ull, 0ull};
        u64t acc3 = 0ull;
#pragma unroll
        for (int pi = 0; pi < 2; pi++) {
#pragma unroll
            for (int p = 0; p < 9; p++) {
                const int h = p / 3, w = p - h * 3;
                const u64t kp = pk2(kk[pi * 18 + p], kk[pi * 18 + 9 + p]);
                fma2(acc1[h], kp, u1pr[pi * 3 + w]);
                fma2(acc2[w], kp, u2pr[pi * 3 + h]);
                fma2(acc3, kp, u3pr[pi * 9 + p]);
                fma2(v4acc[pi], kp, cd[p]);
            }
        }

        float r[7];
#pragma unroll
        for (int j = 0; j < 3; j++) {
            float2 f1 = upk(acc1[j]); r[j] = f1.x + f1.y;
            float2 f2 = upk(acc2[j]); r[3 + j] = f2.x + f2.y;
        }
        { float2 f3 = upk(acc3); r[6] = f3.x + f3.y; }
#pragma unroll
        for (int j = 0; j < 7; j++)
#pragma unroll
            for (int sh = 16; sh > 0; sh >>= 1)
                r[j] += __shfl_xor_sync(0xffffffffu, r[j], sh);
        if (l == 0) {
            const int o = ob + s;
            atomicAdd(&g_v1[o * 3 + 0], r[0]);
            atomicAdd(&g_v1[o * 3 + 1], r[1]);
            atomicAdd(&g_v1[o * 3 + 2], r[2]);
            atomicAdd(&g_v2[o * 3 + 0], r[3]);
            atomicAdd(&g_v2[o * 3 + 1], r[4]);
            atomicAdd(&g_v2[o * 3 + 2], r[5]);
            atomicAdd(&g_v3[o], r[6]);
            // refill just-consumed buffer with stage s+NB (warp-private:
            // all lanes' LDS of this buffer precede this via the shfl chain)
            if (s + NB < OB) {
                mbar_expect_tx(mbw + bi * 8, WSTAGE_BYTES);
                bulk_g2s(bufw_a + bi * WSTAGE_BYTES,
                         Kw + (size_t)(s + NB) * ostr, WSTAGE_BYTES,
                         mbw + bi * 8);
            }
        }
        if (++bi == NB) { bi = 0; par ^= 1; }
    }

    float2 fa = upk(v4acc[0]), fb = upk(v4acc[1]);
    atomicAdd(&g_v4[i0 + 0], fa.x);
    atomicAdd(&g_v4[i0 + 1], fa.y);
    atomicAdd(&g_v4[i0 + 2], fb.x);
    atomicAdd(&g_v4[i0 + 3], fb.y);
}

// ------- U-pass stage 1: w = contract(K, v), REVERSE o traversal -----------
// Reads the o-rows the preceding vpass touched LAST, first -> L2 ping-pong.
__global__ void __launch_bounds__(TB, 4) upass_kernel(const float* __restrict__ K) {
    extern __shared__ __align__(16) float smem[];
    const uint32_t sbase = smem_u32_of(smem);
    float* v1s = smem + TAIL_F;   // 48
    float* v2s = v1s + 48;        // 48
    float* v3s = v2s + 48;        // 16

    const int t = threadIdx.x;
    const int wi = t >> 5, l = t & 31;
    const int ob = blockIdx.x * OB;
    const int by = blockIdx.y;

    const float* Kw = K + ((size_t)ob * I_DIM + by * IB + wi * WIB) * 9;
    const size_t ostr = (size_t)I_DIM * 9;
    const int i0 = by * IB + wi * WIB + l * 4;
    float* bufw = smem + wi * NB * WSTAGE_FLOATS;
    const uint32_t bufw_a = sbase + wi * NB * WSTAGE_BYTES;
    const uint32_t mbw = sbase + MBAR_OFF + wi * NB * 8;

    if (t < 48) { v1s[t] = g_v1[ob * 3 + t]; v2s[t] = g_v2[ob * 3 + t]; }
    if (t < 16) v3s[t] = g_v3[ob + t];
    if (t == 0) {
#pragma unroll
        for (int b = 0; b < NWARP * NB; b++) mbar_init(sbase + MBAR_OFF + b * 8, 1);
        fence_async();
    }
    __syncthreads();
    if (l == 0) {  // prefetch o-rows OB-1, OB-2, OB-3 (reverse traversal)
#pragma unroll
        for (int s = 0; s < NB; s++) {
            mbar_expect_tx(mbw + s * 8, WSTAGE_BYTES);
            bulk_g2s(bufw_a + s * WSTAGE_BYTES,
                     Kw + (size_t)(OB - 1 - s) * ostr, WSTAGE_BYTES, mbw + s * 8);
        }
    }

    u64t v42[2];
    {
        float4 v = *(const float4*)(g_v4 + i0);
        v42[0] = pk2(v.x, v.y);
        v42[1] = pk2(v.z, v.w);
    }

    u64t u1p2[6], u2p2[6], u3p2[18];
#pragma unroll
    for (int j = 0; j < 6; j++) { u1p2[j] = 0ull; u2p2[j] = 0ull; }
#pragma unroll
    for (int j = 0; j < 18; j++) u3p2[j] = 0ull;

    int bi = 0, par = 0;
#pragma unroll 1
    for (int s = 0; s < OB; s++) {
        const int ss = OB - 1 - s;  // reversed o-row index
        mbar_wait(mbw + bi * 8, par);

        const float* kb = bufw + bi * WSTAGE_FLOATS + l * 36;
        float kk[36];
#pragma unroll
        for (int q = 0; q < 9; q++) ld4(kk + q * 4, kb + q * 4);

        u64t b1d[3], b2d[3], b3d;
#pragma unroll
        for (int j = 0; j < 3; j++) {
            const float b1 = v1s[ss * 3 + j]; b1d[j] = pk2(b1, b1);
            const float b2 = v2s[ss * 3 + j]; b2d[j] = pk2(b2, b2);
        }
        { const float b3 = v3s[ss]; b3d = pk2(b3, b3); }

        u64t u4a[9];
#pragma unroll
        for (int p = 0; p < 9; p++) u4a[p] = 0ull;

#pragma unroll
        for (int pi = 0; pi < 2; pi++) {
#pragma unroll
            for (int p = 0; p < 9; p++) {
                const int h = p / 3, w = p - h * 3;
                const u64t kp = pk2(kk[pi * 18 + p], kk[pi * 18 + 9 + p]);
                fma2(u1p2[pi * 3 + w], kp, b1d[h]);
                fma2(u2p2[pi * 3 + h], kp, b2d[w]);
                fma2(u3p2[pi * 9 + p], kp, b3d);
                fma2(u4a[p], kp, v42[pi]);
            }
        }

#pragma unroll
        for (int p = 0; p < 9; p++) {
            float2 f = upk(u4a[p]);
            float v = f.x + f.y;
#pragma unroll
            for (int sh = 16; sh > 0; sh >>= 1)
                v += __shfl_xor_sync(0xffffffffu, v, sh);
            if (l == 0) atomicAdd(&g_u4[(ob + ss) * 9 + p], v);
        }

        if (l == 0 && s + NB < OB) {
            mbar_expect_tx(mbw + bi * 8, WSTAGE_BYTES);
            bulk_g2s(bufw_a + bi * WSTAGE_BYTES,
                     Kw + (size_t)(OB - 1 - (s + NB)) * ostr, WSTAGE_BYTES,
                     mbw + bi * 8);
        }
        if (++bi == NB) { bi = 0; par ^= 1; }
    }

    // deterministic partials for u1/u2/u3 into scratch[go][*]
    float* scr = g_scr + (size_t)blockIdx.x * SCR_STRIDE;
    {
        float o1[12], o2[12];
#pragma unroll
        for (int pi = 0; pi < 2; pi++)
#pragma unroll
            for (int w = 0; w < 3; w++) {
                float2 f1 = upk(u1p2[pi * 3 + w]);
                o1[pi * 6 + w] = f1.x; o1[pi * 6 + 3 + w] = f1.y;
                float2 f2 = upk(u2p2[pi * 3 + w]);
                o2[pi * 6 + w] = f2.x; o2[pi * 6 + 3 + w] = f2.y;
            }
#pragma unroll
        for (int q = 0; q < 3; q++) {
            *(float4*)(scr + i0 * 3 + q * 4) =
                make_float4(o1[q * 4], o1[q * 4 + 1], o1[q * 4 + 2], o1[q * 4 + 3]);
            *(float4*)(scr + 6144 + i0 * 3 + q * 4) =
                make_float4(o2[q * 4], o2[q * 4 + 1], o2[q * 4 + 2], o2[q * 4 + 3]);
        }
        float o3[36];
#pragma unroll
        for (int pi = 0; pi < 2; pi++)
#pragma unroll
            for (int p = 0; p < 9; p++) {
                float2 f = upk(u3p2[pi * 9 + p]);
                o3[pi * 18 + p] = f.x; o3[pi * 18 + 9 + p] = f.y;
            }
#pragma unroll
        for (int q = 0; q < 9; q++)
            *(float4*)(scr + 12288 + i0 * 9 + q * 4) =
                make_float4(o3[q * 4], o3[q * 4 + 1], o3[q * 4 + 2], o3[q * 4 + 3]);
    }
}

// ---- U-pass stage 2: reduce partials, write u, ||w||^2, zero v for next ----
__global__ void ustage2_kernel(int zero_vss) {
    const int b = blockIdx.x, t = threadIdx.x;  // grid 54 x 1024
    if (b < 48) {
        const int e = b * 1024 + t;
        float val;
        int mode;
        if (e < U_ELEMS) {
            float s = 0.f;
#pragma unroll 8
            for (int g = 0; g < GO; g++) s += g_scr[(size_t)g * SCR_STRIDE + e];
            if (b < 6)       { g_u1[e] = s;          mode = 0; }
            else if (b < 12) { g_u2[e - 6144] = s;   mode = 1; }
            else             { g_u3[e - 12288] = s;  mode = 2; }
            val = s;
        } else {
            val = g_u4[e - U_ELEMS];
            mode = 3;
        }
        float tot = block_sum1024(val * val);
        if (t == 0) atomicAdd(&g_wss[mode], tot);
    } else {
        const int e = (b - 48) * 1024 + t;  // 0..6143
        g_v1[e] = 0.f; g_v2[e] = 0.f;
        if (e < O_DIM) { g_v3[e] = 0.f; g_v4[e] = 0.f; }
        if (zero_vss && b == 48 && t < 4) g_vss[t] = 0.f;
    }
}

// ---------------- final: out = K / min_m sigma_m ---------------------------
// Mirrored block index: starts where the final (reverse) upass finished.
__global__ void scale_kernel(const float* __restrict__ K, float* __restrict__ out) {
    float s2min = g_wss[0] / g_vss[0];
#pragma unroll
    for (int m = 1; m < 4; m++) {
        float s2 = g_wss[m] / g_vss[m];
        s2min = fminf(s2min, s2);
    }
    const float inv = rsqrtf(s2min);  // 1/sigma
    const size_t blk = (size_t)(gridDim.x - 1 - blockIdx.x);
    const size_t idx = blk * 1024 + threadIdx.x;
    float4 v = ((const float4*)K)[idx];
    v.x *= inv; v.y *= inv; v.z *= inv; v.w *= inv;
    ((float4*)out)[idx] = v;
}

// ---------------- launch ----------------
extern "C" void kernel_launch(void* const* d_in, const int* in_sizes, int n_in,
                              void* d_out, int out_size) {
    const float* K  = (const float*)d_in[0];
    const float* u1 = (const float*)d_in[1];
    const float* u2 = (const float*)d_in[2];
    const float* u3 = (const float*)d_in[3];
    const float* u4 = (const float*)d_in[4];
    float* out = (float*)d_out;

    static int attr_done = 0;
    if (!attr_done) {
        cudaFuncSetAttribute(vpass_kernel,
                             cudaFuncAttributeMaxDynamicSharedMemorySize, SMEM_DYN);
        cudaFuncSetAttribute(upass_kernel,
                             cudaFuncAttributeMaxDynamicSharedMemorySize, SMEM_DYN);
        // force full 228KB smem carveout so 4 x 56KB blocks co-reside per SM
        cudaFuncSetAttribute(vpass_kernel,
                             cudaFuncAttributePreferredSharedMemoryCarveout, 100);
        cudaFuncSetAttribute(upass_kernel,
                             cudaFuncAttributePreferredSharedMemoryCarveout, 100);
        attr_done = 1;
    }

    dim3 pg(GO, GI);
    zero_v_kernel<<<6, 1024>>>();
    for (int it = 0; it < 3; it++) {
        vpass_kernel<<<pg, TB, SMEM_DYN>>>(K, u1, u2, u3, u4, it == 0 ? 1 : 0);
        vnorm_zero_kernel<<<34, 1024>>>();            // v sumsq + zero u4/wss
        upass_kernel<<<pg, TB, SMEM_DYN>>>(K);
        ustage2_kernel<<<54, 1024>>>(it < 2 ? 1 : 0); // u reduce + w sumsq + zero v
    }
    scale_kernel<<<(O_DIM * I_DIM * 9) / 4096, 1024>>>(K, out);
}